// round 14
// baseline (speedup 1.0000x reference)
#include <cuda_runtime.h>
#include <cuda_bf16.h>

#define NN 512
#define EE (NN * NN)
#define NB 256
#define CHUNK (EE / NB)

// ---------------- scratch ----------------
__device__ int   g_start[NN + 1];
__device__ float g_invcnt[NN];
__device__ int   g_bh[NB * NN];
__device__ int   g_bhoff[NB * NN];
__device__ int   g_src_sorted[EE];
__device__ __align__(16) float g_ea_sorted[EE * 8];
__device__ __align__(16) float g_h1[NN * 36];
__device__ __align__(16) float g_h2[NN * 24];
__device__ __align__(16) float g_h3[NN * 5];

// ---------------- packed f32x2 helpers ----------------
__device__ __forceinline__ unsigned long long pk2(float lo, float hi) {
    unsigned long long r;
    asm("mov.b64 %0,{%1,%2};" : "=l"(r) : "f"(lo), "f"(hi));
    return r;
}
__device__ __forceinline__ void upk2(unsigned long long v, float& lo, float& hi) {
    asm("mov.b64 {%0,%1},%2;" : "=f"(lo), "=f"(hi) : "l"(v));
}
__device__ __forceinline__ unsigned long long ffma2(unsigned long long a,
                                                    unsigned long long b,
                                                    unsigned long long c) {
    unsigned long long d;
    asm("fma.rn.f32x2 %0,%1,%2,%3;" : "=l"(d) : "l"(a), "l"(b), "l"(c));
    return d;
}

// ---------------- cp.async helpers ----------------
__device__ __forceinline__ unsigned s2u(const void* p) {
    return (unsigned)__cvta_generic_to_shared(p);
}
__device__ __forceinline__ void cpa16(unsigned dst, const void* src) {
    asm volatile("cp.async.cg.shared.global [%0], [%1], 16;"
                 :: "r"(dst), "l"(src) : "memory");
}
__device__ __forceinline__ void cpa4(unsigned dst, const void* src) {
    asm volatile("cp.async.ca.shared.global [%0], [%1], 4;"
                 :: "r"(dst), "l"(src) : "memory");
}
#define CP_COMMIT() asm volatile("cp.async.commit_group;" ::: "memory")
template <int N>
__device__ __forceinline__ void cp_wait() {
    asm volatile("cp.async.wait_group %0;" :: "n"(N) : "memory");
}

__device__ __forceinline__ int load_src(const int* raw, int e, int is64) {
    return (is64 ? raw[2 * e] : raw[e]) & (NN - 1);
}
__device__ __forceinline__ int load_dst(const int* raw, int e, int is64) {
    return (is64 ? raw[2 * EE + 2 * e] : raw[EE + e]) & (NN - 1);
}

__device__ __forceinline__ int block_detect_is64(const int* raw, int base, int tid) {
    int found = 0;
    if (tid < 256) {
        int e = base + 4 * tid;
        if (raw[2 * e + 1] != 0) found = 1;
    }
    return (__syncthreads_or(found) == 0) ? 1 : 0;
}

// ---------------- 1: per-block histogram ----------------
__global__ void __launch_bounds__(256) histA_kernel(const int* __restrict__ raw) {
    __shared__ int h[NN];
    int tid = threadIdx.x;
    int base = blockIdx.x * CHUNK;
    int is64 = block_detect_is64(raw, base, tid);
    for (int i = tid; i < NN; i += 256) h[i] = 0;
    __syncthreads();
#pragma unroll
    for (int k = 0; k < CHUNK / 256; k++) {
        int e = base + k * 256 + tid;
        atomicAdd(&h[load_dst(raw, e, is64)], 1);
    }
    __syncthreads();
    for (int i = tid; i < NN; i += 256)
        g_bh[blockIdx.x * NN + i] = h[i];
}

// ---------------- 2: merged totals + scan + offsets ----------------
__global__ void __launch_bounds__(NN) mscan_kernel() {
    __shared__ int sc[NN];
    int t = threadIdx.x;
    int total = 0;
#pragma unroll 8
    for (int blk = 0; blk < NB; blk++) total += g_bh[blk * NN + t];
    sc[t] = total;
    __syncthreads();
    for (int off = 1; off < NN; off <<= 1) {
        int v = (t >= off) ? sc[t - off] : 0;
        __syncthreads();
        sc[t] += v;
        __syncthreads();
    }
    int base = sc[t] - total;
    g_start[t] = base;
    if (t == NN - 1) g_start[NN] = sc[t];
    g_invcnt[t] = 1.0f / (float)(total > 1 ? total : 1);
    int run = base;
#pragma unroll 8
    for (int blk = 0; blk < NB; blk++) {
        g_bhoff[blk * NN + t] = run;
        run += g_bh[blk * NN + t];
    }
}

// ---------------- 3: sorted scatter ----------------
__global__ void __launch_bounds__(256) scatterC_kernel(const int* __restrict__ raw,
                                                       const float* __restrict__ ea) {
    __shared__ int loc[NN];
    int tid = threadIdx.x;
    int base = blockIdx.x * CHUNK;
    int is64 = block_detect_is64(raw, base, tid);
    for (int i = tid; i < NN; i += 256)
        loc[i] = g_bhoff[blockIdx.x * NN + i];
    __syncthreads();
#pragma unroll
    for (int k = 0; k < CHUNK / 256; k++) {
        int e = base + k * 256 + tid;
        int d = load_dst(raw, e, is64);
        int s = load_src(raw, e, is64);
        int pos = atomicAdd(&loc[d], 1);
        const float* q = ea + (size_t)e * 6;
        float v0 = q[0], v1 = q[1], v2 = q[2], v3 = q[3], v4 = q[4], v5 = q[5];
        g_src_sorted[pos] = s;
        float4* w = (float4*)(g_ea_sorted + (size_t)pos * 8);
        w[0] = make_float4(v0, v1, v2, v3);
        w[1] = make_float4(v4, v5, 0.0f, 0.0f);
    }
}

// ---------------- theta tile compute (scalar acc) ----------------
template <int NP>
__device__ __forceinline__ void edge_tile(const ulonglong2* tp,
                                          const unsigned long long* ea2,
                                          float xi, float* acc) {
#pragma unroll
    for (int p = 0; p < NP; p++) {
        ulonglong2 w01 = tp[4 * p + 0];
        ulonglong2 w23 = tp[4 * p + 1];
        ulonglong2 w45 = tp[4 * p + 2];
        ulonglong2 bb  = tp[4 * p + 3];
        unsigned long long t = bb.x;
        t = ffma2(ea2[0], w01.x, t);
        t = ffma2(ea2[1], w01.y, t);
        t = ffma2(ea2[2], w23.x, t);
        t = ffma2(ea2[3], w23.y, t);
        t = ffma2(ea2[4], w45.x, t);
        t = ffma2(ea2[5], w45.y, t);
        float t0, t1; upk2(t, t0, t1);
        acc[2 * p]     = fmaf(xi, fmaxf(t0, 0.0f), acc[2 * p]);
        acc[2 * p + 1] = fmaf(xi, fmaxf(t1, 0.0f), acc[2 * p + 1]);
    }
}

// ---------------- fused NNConv layer: cp.async pipelined edge stream ----------
// Tiles of BLOCK edges; thread tid owns slot tid of each smem buffer (private),
// so the D-deep ring needs no __syncthreads in the main loop.
template <int IN, int OUT, int OPAD, int BLOCK, int D, int MINB>
__global__ void __launch_bounds__(BLOCK, MINB) nnconv_kernel(
    const float* __restrict__ h_in,
    const float* __restrict__ W, const float* __restrict__ b,
    const float* __restrict__ root, const float* __restrict__ bias,
    float* __restrict__ h_out) {
    constexpr int NP = OPAD / 2;
    __shared__ __align__(16) float sW[IN * NP * 16];
    __shared__ __align__(16) float ea_buf[D][BLOCK * 8];
    __shared__ int src_buf[D][BLOCK];
    __shared__ float red[BLOCK / 32][OPAD];
    const int tid = threadIdx.x;

    for (int idx = tid; idx < IN * NP; idx += BLOCK) {
        int i = idx / NP, p = idx % NP;
        float* t = sW + idx * 16;
        int o0 = 2 * p, o1 = 2 * p + 1;
#pragma unroll
        for (int v = 0; v < 6; v++) {
            t[2 * v]     = (o0 < OUT) ? W[v * (IN * OUT) + i * OUT + o0] : 0.0f;
            t[2 * v + 1] = (o1 < OUT) ? W[v * (IN * OUT) + i * OUT + o1] : 0.0f;
        }
        t[12] = (o0 < OUT) ? b[i * OUT + o0] : 0.0f;
        t[13] = (o1 < OUT) ? b[i * OUT + o1] : 0.0f;
        t[14] = 0.0f; t[15] = 0.0f;
    }
    __syncthreads();

    const int n = blockIdx.x;
    const int e0 = g_start[n], e1 = g_start[n + 1];
    const int ntiles = (e1 - e0 + BLOCK - 1) / BLOCK;

    // async-issue tile t into ring slot t%D (thread-private slots)
    auto issue = [&](int t) {
        int g = e0 + t * BLOCK + tid;
        if (t < ntiles && g < e1) {
            unsigned dst = s2u(&ea_buf[t % D][tid * 8]);
            const float* sp = g_ea_sorted + (size_t)g * 8;
            cpa16(dst, sp);
            cpa16(dst + 16, sp + 4);
            cpa4(s2u(&src_buf[t % D][tid]), g_src_sorted + g);
        }
        CP_COMMIT();
    };

#pragma unroll
    for (int k = 0; k < D - 1; k++) issue(k);

    float acc[OPAD];
#pragma unroll
    for (int o = 0; o < OPAD; o++) acc[o] = 0.0f;

    for (int t = 0; t < ntiles; t++) {
        issue(t + D - 1);
        cp_wait<D - 1>();
        int g = e0 + t * BLOCK + tid;
        if (g < e1) {
            const float* eb = &ea_buf[t % D][tid * 8];
            float4 ia = *(const float4*)eb;
            float4 ib = *(const float4*)(eb + 4);
            unsigned long long ea2[6];
            ea2[0] = pk2(ia.x, ia.x); ea2[1] = pk2(ia.y, ia.y);
            ea2[2] = pk2(ia.z, ia.z); ea2[3] = pk2(ia.w, ia.w);
            ea2[4] = pk2(ib.x, ib.x); ea2[5] = pk2(ib.y, ib.y);
            int s = src_buf[t % D][tid];
            if constexpr (IN == 1) {
                edge_tile<NP>((const ulonglong2*)sW, ea2, h_in[s], acc);
            } else {
#pragma unroll 1
                for (int i4 = 0; i4 < IN / 4; i4++) {
                    float4 xv = *(const float4*)(h_in + (size_t)s * IN + 4 * i4);
                    float xs[4] = {xv.x, xv.y, xv.z, xv.w};
#pragma unroll
                    for (int su = 0; su < 4; su++) {
                        const ulonglong2* tp =
                            (const ulonglong2*)(sW + (size_t)(i4 * 4 + su) * NP * 16);
                        edge_tile<NP>(tp, ea2, xs[su], acc);
                    }
                }
            }
        }
    }
    cp_wait<0>();

    // warp reduce
#pragma unroll
    for (int o = 0; o < OPAD; o++) {
        float v = acc[o];
        v += __shfl_down_sync(0xffffffffu, v, 16);
        v += __shfl_down_sync(0xffffffffu, v, 8);
        v += __shfl_down_sync(0xffffffffu, v, 4);
        v += __shfl_down_sync(0xffffffffu, v, 2);
        v += __shfl_down_sync(0xffffffffu, v, 1);
        acc[o] = v;
    }
    if ((tid & 31) == 0) {
#pragma unroll
        for (int o = 0; o < OPAD; o++) red[tid >> 5][o] = acc[o];
    }
    __syncthreads();

    if (tid < OUT) {
        float s = 0.0f;
#pragma unroll
        for (int w = 0; w < BLOCK / 32; w++) s += red[w][tid];
        s *= g_invcnt[n];
        float r = 0.0f;
#pragma unroll
        for (int i = 0; i < IN; i++) r += h_in[(size_t)n * IN + i] * root[i * OUT + tid];
        float v = s + r + bias[tid];
        h_out[(size_t)n * OUT + tid] = fmaxf(v, 0.0f);
    }
}

// ---------------- CBT ----------------
__global__ void cbt_kernel(const float* __restrict__ h3, float* __restrict__ out) {
    __shared__ float sh[NN * 5];
    int tid = threadIdx.x;
    for (int i = tid; i < NN * 5; i += blockDim.x) sh[i] = h3[i];
    __syncthreads();
    int a = blockIdx.x;
    float ha[5];
#pragma unroll
    for (int f = 0; f < 5; f++) ha[f] = sh[a * 5 + f];
    float s = 0.0f;
#pragma unroll
    for (int f = 0; f < 5; f++) s += fabsf(sh[tid * 5 + f] - ha[f]);
    out[(size_t)a * NN + tid] = s;
}

// ---------------- launch ----------------
extern "C" void kernel_launch(void* const* d_in, const int* in_sizes, int n_in,
                              void* d_out, int out_size) {
    const float* x    = (const float*)d_in[0];
    const float* ea   = (const float*)d_in[1];
    const int*   eidx = (const int*)d_in[2];
    const float *W1 = (const float*)d_in[3],  *b1 = (const float*)d_in[4];
    const float *root1 = (const float*)d_in[5], *bias1 = (const float*)d_in[6];
    const float *W2 = (const float*)d_in[7],  *b2 = (const float*)d_in[8];
    const float *root2 = (const float*)d_in[9], *bias2 = (const float*)d_in[10];
    const float *W3 = (const float*)d_in[11], *b3 = (const float*)d_in[12];
    const float *root3 = (const float*)d_in[13], *bias3 = (const float*)d_in[14];
    float* out = (float*)d_out;

    float* h1; cudaGetSymbolAddress((void**)&h1, g_h1);
    float* h2; cudaGetSymbolAddress((void**)&h2, g_h2);
    float* h3; cudaGetSymbolAddress((void**)&h3, g_h3);

    histA_kernel<<<NB, 256>>>(eidx);                                    // 1
    mscan_kernel<<<1, NN>>>();                                          // 2
    scatterC_kernel<<<NB, 256>>>(eidx, ea);                             // 3
    nnconv_kernel<1, 36, 36, 128, 4, 5><<<NN, 128>>>(x,  W1, b1, root1, bias1, h1);  // 4 <- ncu
    nnconv_kernel<36, 24, 24, 128, 3, 4><<<NN, 128>>>(h1, W2, b2, root2, bias2, h2); // 5
    nnconv_kernel<24, 5, 6, 128, 4, 5><<<NN, 128>>>(h2, W3, b3, root3, bias3, h3);   // 6
    cbt_kernel<<<NN, NN>>>(h3, out);                                    // 7
}

// round 15
// speedup vs baseline: 1.0093x; 1.0093x over previous
#include <cuda_runtime.h>
#include <cuda_bf16.h>

#define NN 512
#define EE (NN * NN)
#define NB 256
#define CHUNK (EE / NB)

// ---------------- scratch ----------------
__device__ int   g_done = 0;
__device__ int   g_start[NN + 1];
__device__ float g_invcnt[NN];
__device__ int   g_bh[NB * NN];
__device__ int   g_bhoff[NB * NN];
__device__ int   g_src_sorted[EE];
__device__ __align__(16) float g_ea_sorted[EE * 8];
__device__ __align__(16) float g_h1[NN * 36];
__device__ __align__(16) float g_h2[NN * 24];
__device__ __align__(16) float g_h3[NN * 5];

// ---------------- packed f32x2 helpers ----------------
__device__ __forceinline__ unsigned long long pk2(float lo, float hi) {
    unsigned long long r;
    asm("mov.b64 %0,{%1,%2};" : "=l"(r) : "f"(lo), "f"(hi));
    return r;
}
__device__ __forceinline__ void upk2(unsigned long long v, float& lo, float& hi) {
    asm("mov.b64 {%0,%1},%2;" : "=f"(lo), "=f"(hi) : "l"(v));
}
__device__ __forceinline__ unsigned long long ffma2(unsigned long long a,
                                                    unsigned long long b,
                                                    unsigned long long c) {
    unsigned long long d;
    asm("fma.rn.f32x2 %0,%1,%2,%3;" : "=l"(d) : "l"(a), "l"(b), "l"(c));
    return d;
}

// ---------------- cp.async helpers ----------------
__device__ __forceinline__ unsigned s2u(const void* p) {
    return (unsigned)__cvta_generic_to_shared(p);
}
__device__ __forceinline__ void cpa16(unsigned dst, const void* src) {
    asm volatile("cp.async.cg.shared.global [%0], [%1], 16;"
                 :: "r"(dst), "l"(src) : "memory");
}
__device__ __forceinline__ void cpa4(unsigned dst, const void* src) {
    asm volatile("cp.async.ca.shared.global [%0], [%1], 4;"
                 :: "r"(dst), "l"(src) : "memory");
}
#define CP_COMMIT() asm volatile("cp.async.commit_group;" ::: "memory")
template <int N>
__device__ __forceinline__ void cp_wait() {
    asm volatile("cp.async.wait_group %0;" :: "n"(N) : "memory");
}

__device__ __forceinline__ int load_src(const int* raw, int e, int is64) {
    return (is64 ? raw[2 * e] : raw[e]) & (NN - 1);
}
__device__ __forceinline__ int load_dst(const int* raw, int e, int is64) {
    return (is64 ? raw[2 * EE + 2 * e] : raw[EE + e]) & (NN - 1);
}

__device__ __forceinline__ int block_detect_is64(const int* raw, int base, int tid) {
    int found = 0;
    if (tid < 256) {
        int e = base + 4 * tid;
        if (raw[2 * e + 1] != 0) found = 1;
    }
    return (__syncthreads_or(found) == 0) ? 1 : 0;
}

// ---------------- 1: histogram + (last block) merged scan/offsets ------------
__global__ void __launch_bounds__(256) histA_kernel(const int* __restrict__ raw) {
    __shared__ int h[NN];
    __shared__ int sh_last;
    int tid = threadIdx.x;
    int base = blockIdx.x * CHUNK;
    int is64 = block_detect_is64(raw, base, tid);
    for (int i = tid; i < NN; i += 256) h[i] = 0;
    __syncthreads();
#pragma unroll
    for (int k = 0; k < CHUNK / 256; k++) {
        int e = base + k * 256 + tid;
        atomicAdd(&h[load_dst(raw, e, is64)], 1);
    }
    __syncthreads();
    for (int i = tid; i < NN; i += 256)
        g_bh[blockIdx.x * NN + i] = h[i];

    // last-block does the scan+offsets
    __threadfence();
    __syncthreads();
    if (tid == 0) {
        int v = atomicAdd(&g_done, 1);
        sh_last = (v == NB - 1) ? 1 : 0;
    }
    __syncthreads();
    if (!sh_last) return;

    // ---- merged mscan (256 threads, 2 bins each) ----
    int b0 = 2 * tid, b1 = 2 * tid + 1;
    int tot0 = 0, tot1 = 0;
#pragma unroll 8
    for (int blk = 0; blk < NB; blk++) {
        tot0 += g_bh[blk * NN + b0];
        tot1 += g_bh[blk * NN + b1];
    }
    __syncthreads();           // h[] reuse
    h[tid] = tot0 + tot1;      // pair sums in h[0..255]
    __syncthreads();
    for (int off = 1; off < 256; off <<= 1) {
        int v = (tid >= off) ? h[tid - off] : 0;
        __syncthreads();
        h[tid] += v;
        __syncthreads();
    }
    int basep = h[tid] - (tot0 + tot1);   // exclusive prefix of pair
    g_start[b0] = basep;
    g_start[b1] = basep + tot0;
    if (tid == 255) g_start[NN] = h[255];
    g_invcnt[b0] = 1.0f / (float)(tot0 > 1 ? tot0 : 1);
    g_invcnt[b1] = 1.0f / (float)(tot1 > 1 ? tot1 : 1);
    int run0 = basep, run1 = basep + tot0;
#pragma unroll 8
    for (int blk = 0; blk < NB; blk++) {
        g_bhoff[blk * NN + b0] = run0;
        run0 += g_bh[blk * NN + b0];
        g_bhoff[blk * NN + b1] = run1;
        run1 += g_bh[blk * NN + b1];
    }
    if (tid == 0) g_done = 0;   // reset for next graph replay
}

// ---------------- 2: sorted scatter ----------------
__global__ void __launch_bounds__(256) scatterC_kernel(const int* __restrict__ raw,
                                                       const float* __restrict__ ea) {
    __shared__ int loc[NN];
    int tid = threadIdx.x;
    int base = blockIdx.x * CHUNK;
    int is64 = block_detect_is64(raw, base, tid);
    for (int i = tid; i < NN; i += 256)
        loc[i] = g_bhoff[blockIdx.x * NN + i];
    __syncthreads();
#pragma unroll
    for (int k = 0; k < CHUNK / 256; k++) {
        int e = base + k * 256 + tid;
        int d = load_dst(raw, e, is64);
        int s = load_src(raw, e, is64);
        int pos = atomicAdd(&loc[d], 1);
        const float* q = ea + (size_t)e * 6;
        float v0 = q[0], v1 = q[1], v2 = q[2], v3 = q[3], v4 = q[4], v5 = q[5];
        g_src_sorted[pos] = s;
        float4* w = (float4*)(g_ea_sorted + (size_t)pos * 8);
        w[0] = make_float4(v0, v1, v2, v3);
        w[1] = make_float4(v4, v5, 0.0f, 0.0f);
    }
}

// ---------------- theta tile compute (scalar acc) ----------------
template <int NP>
__device__ __forceinline__ void edge_tile(const ulonglong2* tp,
                                          const unsigned long long* ea2,
                                          float xi, float* acc) {
#pragma unroll
    for (int p = 0; p < NP; p++) {
        ulonglong2 w01 = tp[4 * p + 0];
        ulonglong2 w23 = tp[4 * p + 1];
        ulonglong2 w45 = tp[4 * p + 2];
        ulonglong2 bb  = tp[4 * p + 3];
        unsigned long long t = bb.x;
        t = ffma2(ea2[0], w01.x, t);
        t = ffma2(ea2[1], w01.y, t);
        t = ffma2(ea2[2], w23.x, t);
        t = ffma2(ea2[3], w23.y, t);
        t = ffma2(ea2[4], w45.x, t);
        t = ffma2(ea2[5], w45.y, t);
        float t0, t1; upk2(t, t0, t1);
        acc[2 * p]     = fmaf(xi, fmaxf(t0, 0.0f), acc[2 * p]);
        acc[2 * p + 1] = fmaf(xi, fmaxf(t1, 0.0f), acc[2 * p + 1]);
    }
}

// ---------------- NNConv: cp.async pipeline + output-split (OSP) -------------
// grid = NN*OSP; block bid handles node n=bid/OSP, output-half h=bid%OSP
// (o-pairs [h*NPH, (h+1)*NPH)). Disjoint outputs -> no combine needed.
template <int IN, int OUT, int OPAD, int BLOCK, int D, int OSP, int MINB>
__global__ void __launch_bounds__(BLOCK, MINB) nnconv_kernel(
    const float* __restrict__ h_in,
    const float* __restrict__ W, const float* __restrict__ b,
    const float* __restrict__ root, const float* __restrict__ bias,
    float* __restrict__ h_out) {
    constexpr int NP   = OPAD / 2;
    constexpr int NPH  = NP / OSP;       // tiles owned by this block
    constexpr int OPH  = OPAD / OSP;
    constexpr int OUTH = OUT / OSP;
    __shared__ __align__(16) float sW[IN * NPH * 16];
    __shared__ __align__(16) float ea_buf[D][BLOCK * 8];
    __shared__ int src_buf[D][BLOCK];
    __shared__ float red[BLOCK / 32][OPH];
    const int tid = threadIdx.x;
    const int n = blockIdx.x / OSP;
    const int hh = blockIdx.x % OSP;

    for (int idx = tid; idx < IN * NPH; idx += BLOCK) {
        int i = idx / NPH, pl = idx % NPH;
        int p = hh * NPH + pl;
        float* t = sW + idx * 16;
        int o0 = 2 * p, o1 = 2 * p + 1;
#pragma unroll
        for (int v = 0; v < 6; v++) {
            t[2 * v]     = (o0 < OUT) ? W[v * (IN * OUT) + i * OUT + o0] : 0.0f;
            t[2 * v + 1] = (o1 < OUT) ? W[v * (IN * OUT) + i * OUT + o1] : 0.0f;
        }
        t[12] = (o0 < OUT) ? b[i * OUT + o0] : 0.0f;
        t[13] = (o1 < OUT) ? b[i * OUT + o1] : 0.0f;
        t[14] = 0.0f; t[15] = 0.0f;
    }
    __syncthreads();

    const int e0 = g_start[n], e1 = g_start[n + 1];
    const int ntiles = (e1 - e0 + BLOCK - 1) / BLOCK;

    auto issue = [&](int t) {
        int g = e0 + t * BLOCK + tid;
        if (t < ntiles && g < e1) {
            unsigned dst = s2u(&ea_buf[t % D][tid * 8]);
            const float* sp = g_ea_sorted + (size_t)g * 8;
            cpa16(dst, sp);
            cpa16(dst + 16, sp + 4);
            cpa4(s2u(&src_buf[t % D][tid]), g_src_sorted + g);
        }
        CP_COMMIT();
    };

#pragma unroll
    for (int k = 0; k < D - 1; k++) issue(k);

    float acc[OPH];
#pragma unroll
    for (int o = 0; o < OPH; o++) acc[o] = 0.0f;

    for (int t = 0; t < ntiles; t++) {
        issue(t + D - 1);
        cp_wait<D - 1>();
        int g = e0 + t * BLOCK + tid;
        if (g < e1) {
            const float* eb = &ea_buf[t % D][tid * 8];
            float4 ia = *(const float4*)eb;
            float4 ib = *(const float4*)(eb + 4);
            unsigned long long ea2[6];
            ea2[0] = pk2(ia.x, ia.x); ea2[1] = pk2(ia.y, ia.y);
            ea2[2] = pk2(ia.z, ia.z); ea2[3] = pk2(ia.w, ia.w);
            ea2[4] = pk2(ib.x, ib.x); ea2[5] = pk2(ib.y, ib.y);
            int s = src_buf[t % D][tid];
            if constexpr (IN == 1) {
                edge_tile<NPH>((const ulonglong2*)sW, ea2, h_in[s], acc);
            } else {
#pragma unroll 1
                for (int i4 = 0; i4 < IN / 4; i4++) {
                    float4 xv = *(const float4*)(h_in + (size_t)s * IN + 4 * i4);
                    float xs[4] = {xv.x, xv.y, xv.z, xv.w};
#pragma unroll
                    for (int su = 0; su < 4; su++) {
                        const ulonglong2* tp =
                            (const ulonglong2*)(sW + (size_t)(i4 * 4 + su) * NPH * 16);
                        edge_tile<NPH>(tp, ea2, xs[su], acc);
                    }
                }
            }
        }
    }
    cp_wait<0>();

    // warp reduce
#pragma unroll
    for (int o = 0; o < OPH; o++) {
        float v = acc[o];
        v += __shfl_down_sync(0xffffffffu, v, 16);
        v += __shfl_down_sync(0xffffffffu, v, 8);
        v += __shfl_down_sync(0xffffffffu, v, 4);
        v += __shfl_down_sync(0xffffffffu, v, 2);
        v += __shfl_down_sync(0xffffffffu, v, 1);
        acc[o] = v;
    }
    if ((tid & 31) == 0) {
#pragma unroll
        for (int o = 0; o < OPH; o++) red[tid >> 5][o] = acc[o];
    }
    __syncthreads();

    if (tid < OUTH) {
        int o = hh * OUTH + tid;
        float s = 0.0f;
#pragma unroll
        for (int w = 0; w < BLOCK / 32; w++) s += red[w][tid];
        s *= g_invcnt[n];
        float r = 0.0f;
#pragma unroll
        for (int i = 0; i < IN; i++) r += h_in[(size_t)n * IN + i] * root[i * OUT + o];
        float v = s + r + bias[o];
        h_out[(size_t)n * OUT + o] = fmaxf(v, 0.0f);
    }
}

// ---------------- CBT ----------------
__global__ void cbt_kernel(const float* __restrict__ h3, float* __restrict__ out) {
    __shared__ float sh[NN * 5];
    int tid = threadIdx.x;
    for (int i = tid; i < NN * 5; i += blockDim.x) sh[i] = h3[i];
    __syncthreads();
    int a = blockIdx.x;
    float ha[5];
#pragma unroll
    for (int f = 0; f < 5; f++) ha[f] = sh[a * 5 + f];
    float s = 0.0f;
#pragma unroll
    for (int f = 0; f < 5; f++) s += fabsf(sh[tid * 5 + f] - ha[f]);
    out[(size_t)a * NN + tid] = s;
}

// ---------------- launch ----------------
extern "C" void kernel_launch(void* const* d_in, const int* in_sizes, int n_in,
                              void* d_out, int out_size) {
    const float* x    = (const float*)d_in[0];
    const float* ea   = (const float*)d_in[1];
    const int*   eidx = (const int*)d_in[2];
    const float *W1 = (const float*)d_in[3],  *b1 = (const float*)d_in[4];
    const float *root1 = (const float*)d_in[5], *bias1 = (const float*)d_in[6];
    const float *W2 = (const float*)d_in[7],  *b2 = (const float*)d_in[8];
    const float *root2 = (const float*)d_in[9], *bias2 = (const float*)d_in[10];
    const float *W3 = (const float*)d_in[11], *b3 = (const float*)d_in[12];
    const float *root3 = (const float*)d_in[13], *bias3 = (const float*)d_in[14];
    float* out = (float*)d_out;

    float* h1; cudaGetSymbolAddress((void**)&h1, g_h1);
    float* h2; cudaGetSymbolAddress((void**)&h2, g_h2);
    float* h3; cudaGetSymbolAddress((void**)&h3, g_h3);

    histA_kernel<<<NB, 256>>>(eidx);                                    // 1 (+merged scan)
    scatterC_kernel<<<NB, 256>>>(eidx, ea);                             // 2
    nnconv_kernel<1, 36, 36, 128, 3, 2, 6><<<NN * 2, 128>>>(x,  W1, b1, root1, bias1, h1);  // 3
    nnconv_kernel<36, 24, 24, 128, 2, 2, 7><<<NN * 2, 128>>>(h1, W2, b2, root2, bias2, h2); // 4 <- ncu
    nnconv_kernel<24, 5, 6, 128, 4, 1, 5><<<NN, 128>>>(h2, W3, b3, root3, bias3, h3);       // 5
    cbt_kernel<<<NN, NN>>>(h3, out);                                    // 6
}

// round 16
// speedup vs baseline: 1.1432x; 1.1327x over previous
#include <cuda_runtime.h>
#include <cuda_bf16.h>

#define NN 512
#define EE (NN * NN)
#define NB 256
#define CHUNK (EE / NB)

// ---------------- scratch ----------------
__device__ int   g_done = 0;
__device__ int   g_start[NN + 1];
__device__ float g_invcnt[NN];
__device__ int   g_bh[NB * NN];
__device__ int   g_bhoff[NB * NN];
__device__ int   g_src_sorted[EE];
__device__ __align__(16) float g_ea_sorted[EE * 8];
__device__ __align__(16) float g_h1[NN * 36];
__device__ __align__(16) float g_h2[NN * 24];
__device__ __align__(16) float g_h3[NN * 5];

// ---------------- packed f32x2 helpers ----------------
__device__ __forceinline__ unsigned long long pk2(float lo, float hi) {
    unsigned long long r;
    asm("mov.b64 %0,{%1,%2};" : "=l"(r) : "f"(lo), "f"(hi));
    return r;
}
__device__ __forceinline__ void upk2(unsigned long long v, float& lo, float& hi) {
    asm("mov.b64 {%0,%1},%2;" : "=f"(lo), "=f"(hi) : "l"(v));
}
__device__ __forceinline__ unsigned long long ffma2(unsigned long long a,
                                                    unsigned long long b,
                                                    unsigned long long c) {
    unsigned long long d;
    asm("fma.rn.f32x2 %0,%1,%2,%3;" : "=l"(d) : "l"(a), "l"(b), "l"(c));
    return d;
}

// ---------------- cp.async helpers ----------------
__device__ __forceinline__ unsigned s2u(const void* p) {
    return (unsigned)__cvta_generic_to_shared(p);
}
__device__ __forceinline__ void cpa16(unsigned dst, const void* src) {
    asm volatile("cp.async.cg.shared.global [%0], [%1], 16;"
                 :: "r"(dst), "l"(src) : "memory");
}
__device__ __forceinline__ void cpa4(unsigned dst, const void* src) {
    asm volatile("cp.async.ca.shared.global [%0], [%1], 4;"
                 :: "r"(dst), "l"(src) : "memory");
}
#define CP_COMMIT() asm volatile("cp.async.commit_group;" ::: "memory")
template <int N>
__device__ __forceinline__ void cp_wait() {
    asm volatile("cp.async.wait_group %0;" :: "n"(N) : "memory");
}

__device__ __forceinline__ int load_src(const int* raw, int e, int is64) {
    return (is64 ? raw[2 * e] : raw[e]) & (NN - 1);
}
__device__ __forceinline__ int load_dst(const int* raw, int e, int is64) {
    return (is64 ? raw[2 * EE + 2 * e] : raw[EE + e]) & (NN - 1);
}

__device__ __forceinline__ int block_detect_is64(const int* raw, int base, int tid) {
    int found = 0;
    if (tid < 256) {
        int e = base + 4 * tid;
        if (raw[2 * e + 1] != 0) found = 1;
    }
    return (__syncthreads_or(found) == 0) ? 1 : 0;
}

// ---------------- 1: histogram + (last block) merged scan/offsets ------------
__global__ void __launch_bounds__(256) histA_kernel(const int* __restrict__ raw) {
    __shared__ int h[NN];
    __shared__ int sh_last;
    int tid = threadIdx.x;
    int base = blockIdx.x * CHUNK;
    int is64 = block_detect_is64(raw, base, tid);
    for (int i = tid; i < NN; i += 256) h[i] = 0;
    __syncthreads();
#pragma unroll
    for (int k = 0; k < CHUNK / 256; k++) {
        int e = base + k * 256 + tid;
        atomicAdd(&h[load_dst(raw, e, is64)], 1);
    }
    __syncthreads();
    for (int i = tid; i < NN; i += 256)
        g_bh[blockIdx.x * NN + i] = h[i];

    __threadfence();
    __syncthreads();
    if (tid == 0) {
        int v = atomicAdd(&g_done, 1);
        sh_last = (v == NB - 1) ? 1 : 0;
    }
    __syncthreads();
    if (!sh_last) return;

    int b0 = 2 * tid, b1 = 2 * tid + 1;
    int tot0 = 0, tot1 = 0;
#pragma unroll 8
    for (int blk = 0; blk < NB; blk++) {
        tot0 += g_bh[blk * NN + b0];
        tot1 += g_bh[blk * NN + b1];
    }
    __syncthreads();
    h[tid] = tot0 + tot1;
    __syncthreads();
    for (int off = 1; off < 256; off <<= 1) {
        int v = (tid >= off) ? h[tid - off] : 0;
        __syncthreads();
        h[tid] += v;
        __syncthreads();
    }
    int basep = h[tid] - (tot0 + tot1);
    g_start[b0] = basep;
    g_start[b1] = basep + tot0;
    if (tid == 255) g_start[NN] = h[255];
    g_invcnt[b0] = 1.0f / (float)(tot0 > 1 ? tot0 : 1);
    g_invcnt[b1] = 1.0f / (float)(tot1 > 1 ? tot1 : 1);
    int run0 = basep, run1 = basep + tot0;
#pragma unroll 8
    for (int blk = 0; blk < NB; blk++) {
        g_bhoff[blk * NN + b0] = run0;
        run0 += g_bh[blk * NN + b0];
        g_bhoff[blk * NN + b1] = run1;
        run1 += g_bh[blk * NN + b1];
    }
    if (tid == 0) g_done = 0;
}

// ---------------- 2: sorted scatter ----------------
__global__ void __launch_bounds__(256) scatterC_kernel(const int* __restrict__ raw,
                                                       const float* __restrict__ ea) {
    __shared__ int loc[NN];
    int tid = threadIdx.x;
    int base = blockIdx.x * CHUNK;
    int is64 = block_detect_is64(raw, base, tid);
    for (int i = tid; i < NN; i += 256)
        loc[i] = g_bhoff[blockIdx.x * NN + i];
    __syncthreads();
#pragma unroll
    for (int k = 0; k < CHUNK / 256; k++) {
        int e = base + k * 256 + tid;
        int d = load_dst(raw, e, is64);
        int s = load_src(raw, e, is64);
        int pos = atomicAdd(&loc[d], 1);
        const float* q = ea + (size_t)e * 6;
        float v0 = q[0], v1 = q[1], v2 = q[2], v3 = q[3], v4 = q[4], v5 = q[5];
        g_src_sorted[pos] = s;
        float4* w = (float4*)(g_ea_sorted + (size_t)pos * 8);
        w[0] = make_float4(v0, v1, v2, v3);
        w[1] = make_float4(v4, v5, 0.0f, 0.0f);
    }
}

// ---------------- theta tile compute ----------------
template <int NP>
__device__ __forceinline__ void edge_tile(const ulonglong2* tp,
                                          const unsigned long long* ea2,
                                          float xi, float* acc) {
#pragma unroll
    for (int p = 0; p < NP; p++) {
        ulonglong2 w01 = tp[4 * p + 0];
        ulonglong2 w23 = tp[4 * p + 1];
        ulonglong2 w45 = tp[4 * p + 2];
        ulonglong2 bb  = tp[4 * p + 3];
        unsigned long long t = bb.x;
        t = ffma2(ea2[0], w01.x, t);
        t = ffma2(ea2[1], w01.y, t);
        t = ffma2(ea2[2], w23.x, t);
        t = ffma2(ea2[3], w23.y, t);
        t = ffma2(ea2[4], w45.x, t);
        t = ffma2(ea2[5], w45.y, t);
        float t0, t1; upk2(t, t0, t1);
        acc[2 * p]     = fmaf(xi, fmaxf(t0, 0.0f), acc[2 * p]);
        acc[2 * p + 1] = fmaf(xi, fmaxf(t1, 0.0f), acc[2 * p + 1]);
    }
}

// 2 edges share each W-tile load: halves LDS traffic (the measured bottleneck)
template <int NP>
__device__ __forceinline__ void edge_tile2(const ulonglong2* tp,
                                           const unsigned long long* eaA,
                                           const unsigned long long* eaB,
                                           float xiA, float xiB, float* acc) {
#pragma unroll
    for (int p = 0; p < NP; p++) {
        ulonglong2 w01 = tp[4 * p + 0];
        ulonglong2 w23 = tp[4 * p + 1];
        ulonglong2 w45 = tp[4 * p + 2];
        ulonglong2 bb  = tp[4 * p + 3];
        unsigned long long tA = bb.x, tB = bb.x;
        tA = ffma2(eaA[0], w01.x, tA);  tB = ffma2(eaB[0], w01.x, tB);
        tA = ffma2(eaA[1], w01.y, tA);  tB = ffma2(eaB[1], w01.y, tB);
        tA = ffma2(eaA[2], w23.x, tA);  tB = ffma2(eaB[2], w23.x, tB);
        tA = ffma2(eaA[3], w23.y, tA);  tB = ffma2(eaB[3], w23.y, tB);
        tA = ffma2(eaA[4], w45.x, tA);  tB = ffma2(eaB[4], w45.x, tB);
        tA = ffma2(eaA[5], w45.y, tA);  tB = ffma2(eaB[5], w45.y, tB);
        float a0, a1, b0, b1;
        upk2(tA, a0, a1); upk2(tB, b0, b1);
        float s0 = fmaf(xiA, fmaxf(a0, 0.0f), acc[2 * p]);
        float s1 = fmaf(xiA, fmaxf(a1, 0.0f), acc[2 * p + 1]);
        acc[2 * p]     = fmaf(xiB, fmaxf(b0, 0.0f), s0);
        acc[2 * p + 1] = fmaf(xiB, fmaxf(b1, 0.0f), s1);
    }
}

__device__ __forceinline__ void unpack_ea(const float* eb, unsigned long long* ea2) {
    float4 ia = *(const float4*)eb;
    float4 ib = *(const float4*)(eb + 4);
    ea2[0] = pk2(ia.x, ia.x); ea2[1] = pk2(ia.y, ia.y);
    ea2[2] = pk2(ia.z, ia.z); ea2[3] = pk2(ia.w, ia.w);
    ea2[4] = pk2(ib.x, ib.x); ea2[5] = pk2(ib.y, ib.y);
}

// ---------------- NNConv: cp.async pipeline + output-split + 2-edge tiles -----
// Pipeline tile = 2*BLOCK edges; thread owns edges (g, g+BLOCK) of each tile.
template <int IN, int OUT, int OPAD, int BLOCK, int D, int OSP, int MINB>
__global__ void __launch_bounds__(BLOCK, MINB) nnconv_kernel(
    const float* __restrict__ h_in,
    const float* __restrict__ W, const float* __restrict__ b,
    const float* __restrict__ root, const float* __restrict__ bias,
    float* __restrict__ h_out) {
    constexpr int NP   = OPAD / 2;
    constexpr int NPH  = NP / OSP;
    constexpr int OPH  = OPAD / OSP;
    constexpr int OUTH = OUT / OSP;
    constexpr int TILE = 2 * BLOCK;
    __shared__ __align__(16) float sW[IN * NPH * 16];
    __shared__ __align__(16) float ea_buf[D][TILE * 8];
    __shared__ int src_buf[D][TILE];
    __shared__ float red[BLOCK / 32][OPH];
    const int tid = threadIdx.x;
    const int n = blockIdx.x / OSP;
    const int hh = blockIdx.x % OSP;

    for (int idx = tid; idx < IN * NPH; idx += BLOCK) {
        int i = idx / NPH, pl = idx % NPH;
        int p = hh * NPH + pl;
        float* t = sW + idx * 16;
        int o0 = 2 * p, o1 = 2 * p + 1;
#pragma unroll
        for (int v = 0; v < 6; v++) {
            t[2 * v]     = (o0 < OUT) ? W[v * (IN * OUT) + i * OUT + o0] : 0.0f;
            t[2 * v + 1] = (o1 < OUT) ? W[v * (IN * OUT) + i * OUT + o1] : 0.0f;
        }
        t[12] = (o0 < OUT) ? b[i * OUT + o0] : 0.0f;
        t[13] = (o1 < OUT) ? b[i * OUT + o1] : 0.0f;
        t[14] = 0.0f; t[15] = 0.0f;
    }
    __syncthreads();

    const int e0 = g_start[n], e1 = g_start[n + 1];
    const int ntiles = (e1 - e0 + TILE - 1) / TILE;

    auto issue = [&](int t) {
        if (t < ntiles) {
#pragma unroll
            for (int j = 0; j < 2; j++) {
                int slot = j * BLOCK + tid;
                int g = e0 + t * TILE + slot;
                if (g < e1) {
                    unsigned dst = s2u(&ea_buf[t % D][slot * 8]);
                    const float* sp = g_ea_sorted + (size_t)g * 8;
                    cpa16(dst, sp);
                    cpa16(dst + 16, sp + 4);
                    cpa4(s2u(&src_buf[t % D][slot]), g_src_sorted + g);
                }
            }
        }
        CP_COMMIT();
    };

#pragma unroll
    for (int k = 0; k < D - 1; k++) issue(k);

    float acc[OPH];
#pragma unroll
    for (int o = 0; o < OPH; o++) acc[o] = 0.0f;

    for (int t = 0; t < ntiles; t++) {
        issue(t + D - 1);
        cp_wait<D - 1>();
        int gA = e0 + t * TILE + tid;
        int gB = gA + BLOCK;
        if (gB < e1) {
            unsigned long long eaA[6], eaB[6];
            unpack_ea(&ea_buf[t % D][tid * 8], eaA);
            unpack_ea(&ea_buf[t % D][(BLOCK + tid) * 8], eaB);
            int sA = src_buf[t % D][tid];
            int sB = src_buf[t % D][BLOCK + tid];
            if constexpr (IN == 1) {
                edge_tile2<NPH>((const ulonglong2*)sW, eaA, eaB,
                                h_in[sA], h_in[sB], acc);
            } else {
#pragma unroll 1
                for (int i4 = 0; i4 < IN / 4; i4++) {
                    float4 xvA = *(const float4*)(h_in + (size_t)sA * IN + 4 * i4);
                    float4 xvB = *(const float4*)(h_in + (size_t)sB * IN + 4 * i4);
                    float xsA[4] = {xvA.x, xvA.y, xvA.z, xvA.w};
                    float xsB[4] = {xvB.x, xvB.y, xvB.z, xvB.w};
#pragma unroll
                    for (int su = 0; su < 4; su++) {
                        const ulonglong2* tp =
                            (const ulonglong2*)(sW + (size_t)(i4 * 4 + su) * NPH * 16);
                        edge_tile2<NPH>(tp, eaA, eaB, xsA[su], xsB[su], acc);
                    }
                }
            }
        } else if (gA < e1) {
            unsigned long long ea2[6];
            unpack_ea(&ea_buf[t % D][tid * 8], ea2);
            int s = src_buf[t % D][tid];
            if constexpr (IN == 1) {
                edge_tile<NPH>((const ulonglong2*)sW, ea2, h_in[s], acc);
            } else {
#pragma unroll 1
                for (int i4 = 0; i4 < IN / 4; i4++) {
                    float4 xv = *(const float4*)(h_in + (size_t)s * IN + 4 * i4);
                    float xs[4] = {xv.x, xv.y, xv.z, xv.w};
#pragma unroll
                    for (int su = 0; su < 4; su++) {
                        const ulonglong2* tp =
                            (const ulonglong2*)(sW + (size_t)(i4 * 4 + su) * NPH * 16);
                        edge_tile<NPH>(tp, ea2, xs[su], acc);
                    }
                }
            }
        }
    }
    cp_wait<0>();

    // warp reduce
#pragma unroll
    for (int o = 0; o < OPH; o++) {
        float v = acc[o];
        v += __shfl_down_sync(0xffffffffu, v, 16);
        v += __shfl_down_sync(0xffffffffu, v, 8);
        v += __shfl_down_sync(0xffffffffu, v, 4);
        v += __shfl_down_sync(0xffffffffu, v, 2);
        v += __shfl_down_sync(0xffffffffu, v, 1);
        acc[o] = v;
    }
    if ((tid & 31) == 0) {
#pragma unroll
        for (int o = 0; o < OPH; o++) red[tid >> 5][o] = acc[o];
    }
    __syncthreads();

    if (tid < OUTH) {
        int o = hh * OUTH + tid;
        float s = 0.0f;
#pragma unroll
        for (int w = 0; w < BLOCK / 32; w++) s += red[w][tid];
        s *= g_invcnt[n];
        float r = 0.0f;
#pragma unroll
        for (int i = 0; i < IN; i++) r += h_in[(size_t)n * IN + i] * root[i * OUT + o];
        float v = s + r + bias[o];
        h_out[(size_t)n * OUT + o] = fmaxf(v, 0.0f);
    }
}

// ---------------- CBT ----------------
__global__ void cbt_kernel(const float* __restrict__ h3, float* __restrict__ out) {
    __shared__ float sh[NN * 5];
    int tid = threadIdx.x;
    for (int i = tid; i < NN * 5; i += blockDim.x) sh[i] = h3[i];
    __syncthreads();
    int a = blockIdx.x;
    float ha[5];
#pragma unroll
    for (int f = 0; f < 5; f++) ha[f] = sh[a * 5 + f];
    float s = 0.0f;
#pragma unroll
    for (int f = 0; f < 5; f++) s += fabsf(sh[tid * 5 + f] - ha[f]);
    out[(size_t)a * NN + tid] = s;
}

// ---------------- launch ----------------
extern "C" void kernel_launch(void* const* d_in, const int* in_sizes, int n_in,
                              void* d_out, int out_size) {
    const float* x    = (const float*)d_in[0];
    const float* ea   = (const float*)d_in[1];
    const int*   eidx = (const int*)d_in[2];
    const float *W1 = (const float*)d_in[3],  *b1 = (const float*)d_in[4];
    const float *root1 = (const float*)d_in[5], *bias1 = (const float*)d_in[6];
    const float *W2 = (const float*)d_in[7],  *b2 = (const float*)d_in[8];
    const float *root2 = (const float*)d_in[9], *bias2 = (const float*)d_in[10];
    const float *W3 = (const float*)d_in[11], *b3 = (const float*)d_in[12];
    const float *root3 = (const float*)d_in[13], *bias3 = (const float*)d_in[14];
    float* out = (float*)d_out;

    float* h1; cudaGetSymbolAddress((void**)&h1, g_h1);
    float* h2; cudaGetSymbolAddress((void**)&h2, g_h2);
    float* h3; cudaGetSymbolAddress((void**)&h3, g_h3);

    histA_kernel<<<NB, 256>>>(eidx);                                    // 1 (+merged scan)
    scatterC_kernel<<<NB, 256>>>(eidx, ea);                             // 2
    nnconv_kernel<1, 36, 36, 128, 3, 2, 6><<<NN * 2, 128>>>(x,  W1, b1, root1, bias1, h1);  // 3
    nnconv_kernel<36, 24, 24, 128, 2, 2, 6><<<NN * 2, 128>>>(h1, W2, b2, root2, bias2, h2); // 4 <- ncu
    nnconv_kernel<24, 5, 6, 128, 3, 1, 6><<<NN, 128>>>(h2, W3, b3, root3, bias3, h3);       // 5
    cbt_kernel<<<NN, NN>>>(h3, out);                                    // 6
}

// round 17
// speedup vs baseline: 1.1984x; 1.0483x over previous
#include <cuda_runtime.h>
#include <cuda_bf16.h>

#define NN 512
#define EE (NN * NN)
#define NB 256
#define CHUNK (EE / NB)

// ---------------- scratch ----------------
__device__ int   g_done = 0;
__device__ int   g_start[NN + 1];
__device__ float g_invcnt[NN];
__device__ int   g_bh[NB * NN];
__device__ int   g_bhoff[NB * NN];
__device__ int   g_src_sorted[EE];
__device__ __align__(16) float g_ea_sorted[EE * 8];
__device__ __align__(16) float g_h1[NN * 36];
__device__ __align__(16) float g_h2[NN * 24];
__device__ __align__(16) float g_h3[NN * 5];

// ---------------- packed f32x2 helpers ----------------
__device__ __forceinline__ unsigned long long pk2(float lo, float hi) {
    unsigned long long r;
    asm("mov.b64 %0,{%1,%2};" : "=l"(r) : "f"(lo), "f"(hi));
    return r;
}
__device__ __forceinline__ void upk2(unsigned long long v, float& lo, float& hi) {
    asm("mov.b64 {%0,%1},%2;" : "=f"(lo), "=f"(hi) : "l"(v));
}
__device__ __forceinline__ unsigned long long ffma2(unsigned long long a,
                                                    unsigned long long b,
                                                    unsigned long long c) {
    unsigned long long d;
    asm("fma.rn.f32x2 %0,%1,%2,%3;" : "=l"(d) : "l"(a), "l"(b), "l"(c));
    return d;
}

// ---------------- cp.async helpers ----------------
__device__ __forceinline__ unsigned s2u(const void* p) {
    return (unsigned)__cvta_generic_to_shared(p);
}
__device__ __forceinline__ void cpa16(unsigned dst, const void* src) {
    asm volatile("cp.async.cg.shared.global [%0], [%1], 16;"
                 :: "r"(dst), "l"(src) : "memory");
}
__device__ __forceinline__ void cpa4(unsigned dst, const void* src) {
    asm volatile("cp.async.ca.shared.global [%0], [%1], 4;"
                 :: "r"(dst), "l"(src) : "memory");
}
#define CP_COMMIT() asm volatile("cp.async.commit_group;" ::: "memory")
template <int N>
__device__ __forceinline__ void cp_wait() {
    asm volatile("cp.async.wait_group %0;" :: "n"(N) : "memory");
}

__device__ __forceinline__ int load_src(const int* raw, int e, int is64) {
    return (is64 ? raw[2 * e] : raw[e]) & (NN - 1);
}
__device__ __forceinline__ int load_dst(const int* raw, int e, int is64) {
    return (is64 ? raw[2 * EE + 2 * e] : raw[EE + e]) & (NN - 1);
}

__device__ __forceinline__ int block_detect_is64(const int* raw, int base, int tid) {
    int found = 0;
    if (tid < 256) {
        int e = base + 4 * tid;
        if (raw[2 * e + 1] != 0) found = 1;
    }
    return (__syncthreads_or(found) == 0) ? 1 : 0;
}

// ---------------- 1: histogram + (last block) merged scan/offsets ------------
__global__ void __launch_bounds__(256) histA_kernel(const int* __restrict__ raw) {
    __shared__ int h[NN];
    __shared__ int sh_last;
    int tid = threadIdx.x;
    int base = blockIdx.x * CHUNK;
    int is64 = block_detect_is64(raw, base, tid);
    for (int i = tid; i < NN; i += 256) h[i] = 0;
    __syncthreads();
#pragma unroll
    for (int k = 0; k < CHUNK / 256; k++) {
        int e = base + k * 256 + tid;
        atomicAdd(&h[load_dst(raw, e, is64)], 1);
    }
    __syncthreads();
    for (int i = tid; i < NN; i += 256)
        g_bh[blockIdx.x * NN + i] = h[i];

    __threadfence();
    __syncthreads();
    if (tid == 0) {
        int v = atomicAdd(&g_done, 1);
        sh_last = (v == NB - 1) ? 1 : 0;
    }
    __syncthreads();
    if (!sh_last) return;

    int b0 = 2 * tid, b1 = 2 * tid + 1;
    int tot0 = 0, tot1 = 0;
#pragma unroll 8
    for (int blk = 0; blk < NB; blk++) {
        tot0 += g_bh[blk * NN + b0];
        tot1 += g_bh[blk * NN + b1];
    }
    __syncthreads();
    h[tid] = tot0 + tot1;
    __syncthreads();
    for (int off = 1; off < 256; off <<= 1) {
        int v = (tid >= off) ? h[tid - off] : 0;
        __syncthreads();
        h[tid] += v;
        __syncthreads();
    }
    int basep = h[tid] - (tot0 + tot1);
    g_start[b0] = basep;
    g_start[b1] = basep + tot0;
    if (tid == 255) g_start[NN] = h[255];
    g_invcnt[b0] = 1.0f / (float)(tot0 > 1 ? tot0 : 1);
    g_invcnt[b1] = 1.0f / (float)(tot1 > 1 ? tot1 : 1);
    int run0 = basep, run1 = basep + tot0;
#pragma unroll 8
    for (int blk = 0; blk < NB; blk++) {
        g_bhoff[blk * NN + b0] = run0;
        run0 += g_bh[blk * NN + b0];
        g_bhoff[blk * NN + b1] = run1;
        run1 += g_bh[blk * NN + b1];
    }
    if (tid == 0) g_done = 0;
}

// ---------------- 2: sorted scatter ----------------
__global__ void __launch_bounds__(256) scatterC_kernel(const int* __restrict__ raw,
                                                       const float* __restrict__ ea) {
    __shared__ int loc[NN];
    int tid = threadIdx.x;
    int base = blockIdx.x * CHUNK;
    int is64 = block_detect_is64(raw, base, tid);
    for (int i = tid; i < NN; i += 256)
        loc[i] = g_bhoff[blockIdx.x * NN + i];
    __syncthreads();
#pragma unroll
    for (int k = 0; k < CHUNK / 256; k++) {
        int e = base + k * 256 + tid;
        int d = load_dst(raw, e, is64);
        int s = load_src(raw, e, is64);
        int pos = atomicAdd(&loc[d], 1);
        const float* q = ea + (size_t)e * 6;
        float v0 = q[0], v1 = q[1], v2 = q[2], v3 = q[3], v4 = q[4], v5 = q[5];
        g_src_sorted[pos] = s;
        float4* w = (float4*)(g_ea_sorted + (size_t)pos * 8);
        w[0] = make_float4(v0, v1, v2, v3);
        w[1] = make_float4(v4, v5, 0.0f, 0.0f);
    }
}

// ---------------- theta tile compute: NE edges share each W-tile load ---------
template <int NPH, int NE>
__device__ __forceinline__ void edge_tileN(const ulonglong2* tp,
                                           const unsigned long long ea2[][6],
                                           const float* xi, float* acc) {
#pragma unroll
    for (int p = 0; p < NPH; p++) {
        ulonglong2 w01 = tp[4 * p + 0];
        ulonglong2 w23 = tp[4 * p + 1];
        ulonglong2 w45 = tp[4 * p + 2];
        ulonglong2 bb  = tp[4 * p + 3];
        unsigned long long t[NE];
#pragma unroll
        for (int j = 0; j < NE; j++) t[j] = bb.x;
#pragma unroll
        for (int j = 0; j < NE; j++) t[j] = ffma2(ea2[j][0], w01.x, t[j]);
#pragma unroll
        for (int j = 0; j < NE; j++) t[j] = ffma2(ea2[j][1], w01.y, t[j]);
#pragma unroll
        for (int j = 0; j < NE; j++) t[j] = ffma2(ea2[j][2], w23.x, t[j]);
#pragma unroll
        for (int j = 0; j < NE; j++) t[j] = ffma2(ea2[j][3], w23.y, t[j]);
#pragma unroll
        for (int j = 0; j < NE; j++) t[j] = ffma2(ea2[j][4], w45.x, t[j]);
#pragma unroll
        for (int j = 0; j < NE; j++) t[j] = ffma2(ea2[j][5], w45.y, t[j]);
        float a0 = acc[2 * p], a1 = acc[2 * p + 1];
#pragma unroll
        for (int j = 0; j < NE; j++) {
            float t0, t1; upk2(t[j], t0, t1);
            a0 = fmaf(xi[j], fmaxf(t0, 0.0f), a0);
            a1 = fmaf(xi[j], fmaxf(t1, 0.0f), a1);
        }
        acc[2 * p] = a0; acc[2 * p + 1] = a1;
    }
}

__device__ __forceinline__ void unpack_ea(const float* eb, unsigned long long* ea2) {
    float4 ia = *(const float4*)eb;
    float4 ib = *(const float4*)(eb + 4);
    ea2[0] = pk2(ia.x, ia.x); ea2[1] = pk2(ia.y, ia.y);
    ea2[2] = pk2(ia.z, ia.z); ea2[3] = pk2(ia.w, ia.w);
    ea2[4] = pk2(ib.x, ib.x); ea2[5] = pk2(ib.y, ib.y);
}

// ---------------- NNConv: cp.async pipeline + output-split + NE-edge tiles ----
template <int IN, int OUT, int OPAD, int BLOCK, int D, int OSP, int NE, int MINB>
__global__ void __launch_bounds__(BLOCK, MINB) nnconv_kernel(
    const float* __restrict__ h_in,
    const float* __restrict__ W, const float* __restrict__ b,
    const float* __restrict__ root, const float* __restrict__ bias,
    float* __restrict__ h_out) {
    constexpr int NP   = OPAD / 2;
    constexpr int NPH  = NP / OSP;
    constexpr int OPH  = OPAD / OSP;
    constexpr int OUTH = OUT / OSP;
    constexpr int TILE = NE * BLOCK;
    __shared__ __align__(16) float sW[IN * NPH * 16];
    __shared__ __align__(16) float ea_buf[D][TILE * 8];
    __shared__ int src_buf[D][TILE];
    __shared__ float red[BLOCK / 32][OPH];
    const int tid = threadIdx.x;
    const int n = blockIdx.x / OSP;
    const int hh = blockIdx.x % OSP;

    for (int idx = tid; idx < IN * NPH; idx += BLOCK) {
        int i = idx / NPH, pl = idx % NPH;
        int p = hh * NPH + pl;
        float* t = sW + idx * 16;
        int o0 = 2 * p, o1 = 2 * p + 1;
#pragma unroll
        for (int v = 0; v < 6; v++) {
            t[2 * v]     = (o0 < OUT) ? W[v * (IN * OUT) + i * OUT + o0] : 0.0f;
            t[2 * v + 1] = (o1 < OUT) ? W[v * (IN * OUT) + i * OUT + o1] : 0.0f;
        }
        t[12] = (o0 < OUT) ? b[i * OUT + o0] : 0.0f;
        t[13] = (o1 < OUT) ? b[i * OUT + o1] : 0.0f;
        t[14] = 0.0f; t[15] = 0.0f;
    }
    __syncthreads();

    const int e0 = g_start[n], e1 = g_start[n + 1];
    const int ntiles = (e1 - e0 + TILE - 1) / TILE;

    auto issue = [&](int t) {
        if (t < ntiles) {
#pragma unroll
            for (int j = 0; j < NE; j++) {
                int slot = j * BLOCK + tid;
                int g = e0 + t * TILE + slot;
                if (g < e1) {
                    unsigned dst = s2u(&ea_buf[t % D][slot * 8]);
                    const float* sp = g_ea_sorted + (size_t)g * 8;
                    cpa16(dst, sp);
                    cpa16(dst + 16, sp + 4);
                    cpa4(s2u(&src_buf[t % D][slot]), g_src_sorted + g);
                }
            }
        }
        CP_COMMIT();
    };

#pragma unroll
    for (int k = 0; k < D - 1; k++) issue(k);

    float acc[OPH];
#pragma unroll
    for (int o = 0; o < OPH; o++) acc[o] = 0.0f;

    for (int t = 0; t < ntiles; t++) {
        issue(t + D - 1);
        cp_wait<D - 1>();
        int gbase = e0 + t * TILE + tid;
        if (gbase + (NE - 1) * BLOCK < e1) {
            // full NE-edge path
            unsigned long long ea2[NE][6];
            int s[NE];
#pragma unroll
            for (int j = 0; j < NE; j++) {
                unpack_ea(&ea_buf[t % D][(j * BLOCK + tid) * 8], ea2[j]);
                s[j] = src_buf[t % D][j * BLOCK + tid];
            }
            if constexpr (IN == 1) {
                float xi[NE];
#pragma unroll
                for (int j = 0; j < NE; j++) xi[j] = h_in[s[j]];
                edge_tileN<NPH, NE>((const ulonglong2*)sW, ea2, xi, acc);
            } else {
#pragma unroll 1
                for (int i4 = 0; i4 < IN / 4; i4++) {
                    float4 xv[NE];
#pragma unroll
                    for (int j = 0; j < NE; j++)
                        xv[j] = *(const float4*)(h_in + (size_t)s[j] * IN + 4 * i4);
#pragma unroll
                    for (int su = 0; su < 4; su++) {
                        float xi[NE];
#pragma unroll
                        for (int j = 0; j < NE; j++)
                            xi[j] = (su == 0) ? xv[j].x : (su == 1) ? xv[j].y
                                  : (su == 2) ? xv[j].z : xv[j].w;
                        const ulonglong2* tp =
                            (const ulonglong2*)(sW + (size_t)(i4 * 4 + su) * NPH * 16);
                        edge_tileN<NPH, NE>(tp, ea2, xi, acc);
                    }
                }
            }
        } else {
            // partial tile: per-edge fallback
#pragma unroll
            for (int j = 0; j < NE; j++) {
                int g = gbase + j * BLOCK;
                if (g < e1) {
                    unsigned long long ea2[1][6];
                    unpack_ea(&ea_buf[t % D][(j * BLOCK + tid) * 8], ea2[0]);
                    int s = src_buf[t % D][j * BLOCK + tid];
                    if constexpr (IN == 1) {
                        float xi[1] = {h_in[s]};
                        edge_tileN<NPH, 1>((const ulonglong2*)sW, ea2, xi, acc);
                    } else {
#pragma unroll 1
                        for (int i4 = 0; i4 < IN / 4; i4++) {
                            float4 xv = *(const float4*)(h_in + (size_t)s * IN + 4 * i4);
                            float xs[4] = {xv.x, xv.y, xv.z, xv.w};
#pragma unroll
                            for (int su = 0; su < 4; su++) {
                                const ulonglong2* tp =
                                    (const ulonglong2*)(sW + (size_t)(i4 * 4 + su) * NPH * 16);
                                float xi[1] = {xs[su]};
                                edge_tileN<NPH, 1>(tp, ea2, xi, acc);
                            }
                        }
                    }
                }
            }
        }
    }
    cp_wait<0>();

    // warp reduce
#pragma unroll
    for (int o = 0; o < OPH; o++) {
        float v = acc[o];
        v += __shfl_down_sync(0xffffffffu, v, 16);
        v += __shfl_down_sync(0xffffffffu, v, 8);
        v += __shfl_down_sync(0xffffffffu, v, 4);
        v += __shfl_down_sync(0xffffffffu, v, 2);
        v += __shfl_down_sync(0xffffffffu, v, 1);
        acc[o] = v;
    }
    if ((tid & 31) == 0) {
#pragma unroll
        for (int o = 0; o < OPH; o++) red[tid >> 5][o] = acc[o];
    }
    __syncthreads();

    if (tid < OUTH) {
        int o = hh * OUTH + tid;
        float s = 0.0f;
#pragma unroll
        for (int w = 0; w < BLOCK / 32; w++) s += red[w][tid];
        s *= g_invcnt[n];
        float r = 0.0f;
#pragma unroll
        for (int i = 0; i < IN; i++) r += h_in[(size_t)n * IN + i] * root[i * OUT + o];
        float v = s + r + bias[o];
        h_out[(size_t)n * OUT + o] = fmaxf(v, 0.0f);
    }
}

// ---------------- CBT ----------------
__global__ void cbt_kernel(const float* __restrict__ h3, float* __restrict__ out) {
    __shared__ float sh[NN * 5];
    int tid = threadIdx.x;
    for (int i = tid; i < NN * 5; i += blockDim.x) sh[i] = h3[i];
    __syncthreads();
    int a = blockIdx.x;
    float ha[5];
#pragma unroll
    for (int f = 0; f < 5; f++) ha[f] = sh[a * 5 + f];
    float s = 0.0f;
#pragma unroll
    for (int f = 0; f < 5; f++) s += fabsf(sh[tid * 5 + f] - ha[f]);
    out[(size_t)a * NN + tid] = s;
}

// ---------------- launch ----------------
extern "C" void kernel_launch(void* const* d_in, const int* in_sizes, int n_in,
                              void* d_out, int out_size) {
    const float* x    = (const float*)d_in[0];
    const float* ea   = (const float*)d_in[1];
    const int*   eidx = (const int*)d_in[2];
    const float *W1 = (const float*)d_in[3],  *b1 = (const float*)d_in[4];
    const float *root1 = (const float*)d_in[5], *bias1 = (const float*)d_in[6];
    const float *W2 = (const float*)d_in[7],  *b2 = (const float*)d_in[8];
    const float *root2 = (const float*)d_in[9], *bias2 = (const float*)d_in[10];
    const float *W3 = (const float*)d_in[11], *b3 = (const float*)d_in[12];
    const float *root3 = (const float*)d_in[13], *bias3 = (const float*)d_in[14];
    float* out = (float*)d_out;

    float* h1; cudaGetSymbolAddress((void**)&h1, g_h1);
    float* h2; cudaGetSymbolAddress((void**)&h2, g_h2);
    float* h3; cudaGetSymbolAddress((void**)&h3, g_h3);

    histA_kernel<<<NB, 256>>>(eidx);                                    // 1 (+merged scan)
    scatterC_kernel<<<NB, 256>>>(eidx, ea);                             // 2
    // <IN, OUT, OPAD, BLOCK, D, OSP, NE, MINB>
    nnconv_kernel<1, 36, 36, 128, 2, 2, 3, 6><<<NN * 2, 128>>>(x,  W1, b1, root1, bias1, h1);  // 3
    nnconv_kernel<36, 24, 24, 128, 2, 2, 3, 5><<<NN * 2, 128>>>(h1, W2, b2, root2, bias2, h2); // 4 <- ncu
    nnconv_kernel<24, 5, 6, 128, 2, 1, 3, 6><<<NN, 128>>>(h2, W3, b3, root3, bias3, h3);       // 5
    cbt_kernel<<<NN, NN>>>(h3, out);                                    // 6
}